// round 7
// baseline (speedup 1.0000x reference)
#include <cuda_runtime.h>
#include <cuda_fp16.h>
#include <cstdint>

#define FDIM 64
#define TWOF 128
#define NMAX 100000
#define BETA 0.5f
#define NEGSLOPE 0.01f

// fp16 scratch: P[n][0:64]=h@W1^T, P[n][64:128]=h@W2^T+b ; hh = h in fp16
static __device__ __align__(16) __half g_Ph[(size_t)NMAX * TWOF];
static __device__ __align__(16) __half g_hh[(size_t)NMAX * FDIM];
static __device__ __align__(16) float g_Wt[FDIM * TWOF];   // [k][c] transposed weights
static __device__ __align__(16) float g_colsum[FDIM];
static __device__ __align__(16) float g_inv[FDIM];
static __device__ unsigned g_mm[4];

__device__ __forceinline__ unsigned encf(float f) {
    unsigned u = __float_as_uint(f);
    return (u & 0x80000000u) ? ~u : (u | 0x80000000u);
}
__device__ __forceinline__ float decf(unsigned u) {
    return (u & 0x80000000u) ? __uint_as_float(u & 0x7FFFFFFFu) : __uint_as_float(~u);
}

// packed f32x2 fma: d = a*b + d  (FFMA2 in SASS; only reachable via PTX)
__device__ __forceinline__ void ffma2(unsigned long long& d, unsigned long long a,
                                      unsigned long long b) {
    asm("fma.rn.f32x2 %0, %1, %2, %3;" : "=l"(d) : "l"(a), "l"(b), "l"(d));
}
__device__ __forceinline__ unsigned long long dup2(float x) {
    unsigned long long d;
    unsigned u = __float_as_uint(x);
    asm("mov.b64 %0, {%1, %1};" : "=l"(d) : "r"(u));
    return d;
}
__device__ __forceinline__ void unpack2(unsigned long long v, float& lo, float& hi) {
    unsigned a, b;
    asm("mov.b64 {%0, %1}, %2;" : "=r"(a), "=r"(b) : "l"(v));
    lo = __uint_as_float(a);
    hi = __uint_as_float(b);
}

__global__ void k_init() {
    int t = threadIdx.x;
    if (t < FDIM) g_colsum[t] = 0.0f;
    if (t == 0) {
        g_mm[0] = 0xFFFFFFFFu;
        g_mm[1] = 0u;
        g_mm[2] = 0xFFFFFFFFu;
        g_mm[3] = 0u;
    }
}

// One-time weight transpose: g_Wt[k*128+c] = Wt[c][k].
__global__ void k_wprep(const float* __restrict__ fc_w) {
    int idx = blockIdx.x * 256 + threadIdx.x;
    if (idx >= FDIM * TWOF) return;
    int k = idx >> 7, c = idx & 127;
    g_Wt[idx] = (c < FDIM) ? fc_w[c * TWOF + k]
                           : fc_w[(c - FDIM) * TWOF + FDIM + k];
}

// One-time h -> fp16
__global__ void __launch_bounds__(256) k_hprep(const float* __restrict__ h, int total4) {
    int i = blockIdx.x * 256 + threadIdx.x;
    if (i >= total4) return;
    float4 v = ((const float4*)h)[i];
    __half2 a = __floats2half2_rn(v.x, v.y);
    __half2 b = __floats2half2_rn(v.z, v.w);
    uint2 pk;
    pk.x = *(unsigned*)&a;
    pk.y = *(unsigned*)&b;
    ((uint2*)g_hh)[i] = pk;
}

__global__ void k_minmax(const float* __restrict__ amount,
                         const float* __restrict__ count, int E) {
    int stride = gridDim.x * blockDim.x;
    int i0 = blockIdx.x * blockDim.x + threadIdx.x;
    float amin = INFINITY, amax = -INFINITY, cmin = INFINITY, cmax = -INFINITY;
    int E4 = E >> 2;
    const float4* a4 = (const float4*)amount;
    const float4* c4 = (const float4*)count;
    for (int i = i0; i < E4; i += stride) {
        float4 a = a4[i], c = c4[i];
        amin = fminf(amin, fminf(fminf(a.x, a.y), fminf(a.z, a.w)));
        amax = fmaxf(amax, fmaxf(fmaxf(a.x, a.y), fmaxf(a.z, a.w)));
        cmin = fminf(cmin, fminf(fminf(c.x, c.y), fminf(c.z, c.w)));
        cmax = fmaxf(cmax, fmaxf(fmaxf(c.x, c.y), fmaxf(c.z, c.w)));
    }
    for (int i = (E4 << 2) + i0; i < E; i += stride) {
        float a = amount[i], c = count[i];
        amin = fminf(amin, a); amax = fmaxf(amax, a);
        cmin = fminf(cmin, c); cmax = fmaxf(cmax, c);
    }
    #pragma unroll
    for (int off = 16; off; off >>= 1) {
        amin = fminf(amin, __shfl_down_sync(0xFFFFFFFFu, amin, off));
        amax = fmaxf(amax, __shfl_down_sync(0xFFFFFFFFu, amax, off));
        cmin = fminf(cmin, __shfl_down_sync(0xFFFFFFFFu, cmin, off));
        cmax = fmaxf(cmax, __shfl_down_sync(0xFFFFFFFFu, cmax, off));
    }
    if ((threadIdx.x & 31) == 0) {
        atomicMin(&g_mm[0], encf(amin));
        atomicMax(&g_mm[1], encf(amax));
        atomicMin(&g_mm[2], encf(cmin));
        atomicMax(&g_mm[3], encf(cmax));
    }
}

// Projection GEMM, FFMA2, fp16 output. 64 nodes/block, 256 threads:
// tx(0..15) -> 8 cols, ty(0..15) -> 4 nodes. acc = 16 ull regs.
#define GN 64
__global__ void __launch_bounds__(256) k_gemm(const float* __restrict__ h,
                                              const float* __restrict__ fc_b, int N) {
    __shared__ __align__(16) float hs[GN][68];
    int n0 = blockIdx.x * GN;
    int tid = threadIdx.x;

    {
        const float4* h4 = (const float4*)h;
        for (int idx = tid; idx < GN * (FDIM / 4); idx += 256) {
            int n = idx >> 4, kq = idx & 15;
            int gn = n0 + n;
            float4 v = (gn < N) ? h4[(size_t)gn * (FDIM / 4) + kq]
                                : make_float4(0.f, 0.f, 0.f, 0.f);
            *(float4*)&hs[n][kq * 4] = v;
        }
    }
    __syncthreads();

    int tx = tid & 15, ty = tid >> 4;
    int c0 = tx * 8;
    int nb = ty * 4;

    unsigned long long acc[4][4];
    #pragma unroll
    for (int i = 0; i < 4; i++)
        #pragma unroll
        for (int j = 0; j < 4; j++) acc[i][j] = 0ull;

    #pragma unroll 4
    for (int k = 0; k < FDIM; k++) {
        const ulonglong2* bp = (const ulonglong2*)(g_Wt + k * TWOF + c0);
        ulonglong2 b01 = __ldg(bp);
        ulonglong2 b23 = __ldg(bp + 1);
        #pragma unroll
        for (int i = 0; i < 4; i++) {
            unsigned long long a2 = dup2(hs[nb + i][k]);
            ffma2(acc[i][0], a2, b01.x);
            ffma2(acc[i][1], a2, b01.y);
            ffma2(acc[i][2], a2, b23.x);
            ffma2(acc[i][3], a2, b23.y);
        }
    }

    float bias[8];
    #pragma unroll
    for (int j = 0; j < 8; j++)
        bias[j] = (c0 >= FDIM) ? __ldg(&fc_b[c0 + j - FDIM]) : 0.0f;

    #pragma unroll
    for (int i = 0; i < 4; i++) {
        int gn = n0 + nb + i;
        if (gn >= N) continue;
        float o[8];
        #pragma unroll
        for (int j = 0; j < 4; j++) unpack2(acc[i][j], o[2 * j], o[2 * j + 1]);
        __half2 ha = __floats2half2_rn(o[0] + bias[0], o[1] + bias[1]);
        __half2 hb = __floats2half2_rn(o[2] + bias[2], o[3] + bias[3]);
        __half2 hc = __floats2half2_rn(o[4] + bias[4], o[5] + bias[5]);
        __half2 hd = __floats2half2_rn(o[6] + bias[6], o[7] + bias[7]);
        uint4 pk;
        pk.x = *(unsigned*)&ha; pk.y = *(unsigned*)&hb;
        pk.z = *(unsigned*)&hc; pk.w = *(unsigned*)&hd;
        *(uint4*)(g_Ph + (size_t)gn * TWOF + c0) = pk;  // 16B aligned: c0 % 8 == 0
    }
}

// RED without memory clobber: compiler may hoist later gathers above it.
__device__ __forceinline__ void red_add_v4(float* p, float x, float y, float z, float w) {
    asm volatile("red.global.add.v4.f32 [%0], {%1, %2, %3, %4};"
                 :: "l"(p), "f"(x), "f"(y), "f"(z), "f"(w));
}

__device__ __forceinline__ float lrelu_ew(float s, float ew) {
    return (s >= 0.f ? s : NEGSLOPE * s) * ew;
}

// unpack uint2 holding 4 halves into float4
__device__ __forceinline__ float4 h4_to_f4(uint2 p) {
    float2 lo = __half22float2(*(__half2*)&p.x);
    float2 hi = __half22float2(*(__half2*)&p.y);
    return make_float4(lo.x, lo.y, hi.x, hi.y);
}

// FUSED edge pass, fp16 gathers, 4 edges per 16-lane group per iteration.
__global__ void __launch_bounds__(256) k_edge(const float* __restrict__ amount,
                                              const float* __restrict__ count,
                                              const int* __restrict__ adj,
                                              float* __restrict__ out, int E) {
    const int* srcA = adj;
    const int* dstA = adj + E;
    int lane16 = threadIdx.x & 15;
    int egrp = threadIdx.x >> 4;
    int co = lane16 * 4;

    float amin = decf(g_mm[0]), amax = decf(g_mm[1]);
    float cmin = decf(g_mm[2]), cmax = decf(g_mm[3]);
    float as = BETA / (amax - amin + 1e-8f);
    float cs = (1.0f - BETA) / (cmax - cmin + 1e-8f);

    float4 acc = make_float4(0.f, 0.f, 0.f, 0.f);

    int g0 = blockIdx.x * 16 + egrp;
    int gstride = gridDim.x * 16;
    int E4 = E >> 2;

    for (int g = g0; g < E4; g += gstride) {
        int e0 = g * 4;
        int4 s4 = *(const int4*)(srcA + e0);
        int4 d4 = *(const int4*)(dstA + e0);
        float4 am = *(const float4*)(amount + e0);
        float4 ct = *(const float4*)(count + e0);

        uint2 q1a = *(const uint2*)(g_Ph + (size_t)s4.x * TWOF + co);
        uint2 q1b = *(const uint2*)(g_Ph + (size_t)s4.y * TWOF + co);
        uint2 q1c = *(const uint2*)(g_Ph + (size_t)s4.z * TWOF + co);
        uint2 q1d = *(const uint2*)(g_Ph + (size_t)s4.w * TWOF + co);
        uint2 q2a = *(const uint2*)(g_Ph + (size_t)d4.x * TWOF + FDIM + co);
        uint2 q2b = *(const uint2*)(g_Ph + (size_t)d4.y * TWOF + FDIM + co);
        uint2 q2c = *(const uint2*)(g_Ph + (size_t)d4.z * TWOF + FDIM + co);
        uint2 q2d = *(const uint2*)(g_Ph + (size_t)d4.w * TWOF + FDIM + co);
        uint2 qha = *(const uint2*)(g_hh + (size_t)d4.x * FDIM + co);
        uint2 qhb = *(const uint2*)(g_hh + (size_t)d4.y * FDIM + co);
        uint2 qhc = *(const uint2*)(g_hh + (size_t)d4.z * FDIM + co);
        uint2 qhd = *(const uint2*)(g_hh + (size_t)d4.w * FDIM + co);

        float ew0 = (am.x - amin) * as + (ct.x - cmin) * cs;
        float ew1 = (am.y - amin) * as + (ct.y - cmin) * cs;
        float ew2 = (am.z - amin) * as + (ct.z - cmin) * cs;
        float ew3 = (am.w - amin) * as + (ct.w - cmin) * cs;

        {
            float4 p1 = h4_to_f4(q1a), p2 = h4_to_f4(q2a), hv = h4_to_f4(qha);
            float ex = __expf(lrelu_ew(p1.x + p2.x, ew0));
            float ey = __expf(lrelu_ew(p1.y + p2.y, ew0));
            float ez = __expf(lrelu_ew(p1.z + p2.z, ew0));
            float ew_ = __expf(lrelu_ew(p1.w + p2.w, ew0));
            acc.x += ex; acc.y += ey; acc.z += ez; acc.w += ew_;
            red_add_v4(out + (size_t)s4.x * FDIM + co,
                       ex * hv.x, ey * hv.y, ez * hv.z, ew_ * hv.w);
        }
        {
            float4 p1 = h4_to_f4(q1b), p2 = h4_to_f4(q2b), hv = h4_to_f4(qhb);
            float ex = __expf(lrelu_ew(p1.x + p2.x, ew1));
            float ey = __expf(lrelu_ew(p1.y + p2.y, ew1));
            float ez = __expf(lrelu_ew(p1.z + p2.z, ew1));
            float ew_ = __expf(lrelu_ew(p1.w + p2.w, ew1));
            acc.x += ex; acc.y += ey; acc.z += ez; acc.w += ew_;
            red_add_v4(out + (size_t)s4.y * FDIM + co,
                       ex * hv.x, ey * hv.y, ez * hv.z, ew_ * hv.w);
        }
        {
            float4 p1 = h4_to_f4(q1c), p2 = h4_to_f4(q2c), hv = h4_to_f4(qhc);
            float ex = __expf(lrelu_ew(p1.x + p2.x, ew2));
            float ey = __expf(lrelu_ew(p1.y + p2.y, ew2));
            float ez = __expf(lrelu_ew(p1.z + p2.z, ew2));
            float ew_ = __expf(lrelu_ew(p1.w + p2.w, ew2));
            acc.x += ex; acc.y += ey; acc.z += ez; acc.w += ew_;
            red_add_v4(out + (size_t)s4.z * FDIM + co,
                       ex * hv.x, ey * hv.y, ez * hv.z, ew_ * hv.w);
        }
        {
            float4 p1 = h4_to_f4(q1d), p2 = h4_to_f4(q2d), hv = h4_to_f4(qhd);
            float ex = __expf(lrelu_ew(p1.x + p2.x, ew3));
            float ey = __expf(lrelu_ew(p1.y + p2.y, ew3));
            float ez = __expf(lrelu_ew(p1.z + p2.z, ew3));
            float ew_ = __expf(lrelu_ew(p1.w + p2.w, ew3));
            acc.x += ex; acc.y += ey; acc.z += ez; acc.w += ew_;
            red_add_v4(out + (size_t)s4.w * FDIM + co,
                       ex * hv.x, ey * hv.y, ez * hv.z, ew_ * hv.w);
        }
    }

    // tail (E % 4), one group only
    if (blockIdx.x == 0 && egrp == 0) {
        for (int e = E & ~3; e < E; e++) {
            int s = srcA[e], d = dstA[e];
            float ew = (amount[e] - amin) * as + (count[e] - cmin) * cs;
            float4 p1 = h4_to_f4(*(const uint2*)(g_Ph + (size_t)s * TWOF + co));
            float4 p2 = h4_to_f4(*(const uint2*)(g_Ph + (size_t)d * TWOF + FDIM + co));
            float4 hv = h4_to_f4(*(const uint2*)(g_hh + (size_t)d * FDIM + co));
            float ex = __expf(lrelu_ew(p1.x + p2.x, ew));
            float ey = __expf(lrelu_ew(p1.y + p2.y, ew));
            float ez = __expf(lrelu_ew(p1.z + p2.z, ew));
            float ew_ = __expf(lrelu_ew(p1.w + p2.w, ew));
            acc.x += ex; acc.y += ey; acc.z += ez; acc.w += ew_;
            red_add_v4(out + (size_t)s * FDIM + co,
                       ex * hv.x, ey * hv.y, ez * hv.z, ew_ * hv.w);
        }
    }

    __shared__ float scol[FDIM];
    if (threadIdx.x < FDIM) scol[threadIdx.x] = 0.0f;
    __syncthreads();
    atomicAdd(&scol[co + 0], acc.x);
    atomicAdd(&scol[co + 1], acc.y);
    atomicAdd(&scol[co + 2], acc.z);
    atomicAdd(&scol[co + 3], acc.w);
    __syncthreads();
    if (threadIdx.x < FDIM) atomicAdd(&g_colsum[threadIdx.x], scol[threadIdx.x]);
}

__global__ void k_inv() {
    int t = threadIdx.x;
    if (t < FDIM) g_inv[t] = 1.0f / g_colsum[t];
}

__global__ void __launch_bounds__(256) k_norm(float* __restrict__ out, int total4) {
    int i = blockIdx.x * blockDim.x + threadIdx.x;
    if (i >= total4) return;
    float4 inv = *(const float4*)(g_inv + (i & 15) * 4);
    float4 v = ((float4*)out)[i];
    v.x *= inv.x; v.y *= inv.y; v.z *= inv.z; v.w *= inv.w;
    ((float4*)out)[i] = v;
}

extern "C" void kernel_launch(void* const* d_in, const int* in_sizes, int n_in,
                              void* d_out, int out_size) {
    const float* h = (const float*)d_in[0];
    const int* adj = (const int*)d_in[1];
    const float* amount = (const float*)d_in[2];
    const float* count = (const float*)d_in[3];
    const float* fc_w = (const float*)d_in[4];
    const float* fc_b = (const float*)d_in[5];
    float* out = (float*)d_out;

    int N = in_sizes[0] / FDIM;
    int E = in_sizes[2];
    int htotal4 = (N * FDIM) / 4;

    k_init<<<1, 64>>>();
    k_wprep<<<(FDIM * TWOF + 255) / 256, 256>>>(fc_w);
    k_hprep<<<(htotal4 + 255) / 256, 256>>>(h, htotal4);
    cudaMemsetAsync(d_out, 0, (size_t)out_size * sizeof(float));
    k_minmax<<<512, 256>>>(amount, count, E);
    k_gemm<<<(N + GN - 1) / GN, 256>>>(h, fc_b, N);
    k_edge<<<1184, 256>>>(amount, count, adj, out, E);
    k_inv<<<1, 64>>>();
    int total4 = out_size / 4;
    k_norm<<<(total4 + 255) / 256, 256>>>(out, total4);
}